// round 16
// baseline (speedup 1.0000x reference)
#include <cuda_runtime.h>
#include <cuda_fp16.h>
#include <math.h>
#include <cstdint>

#define NB 2
#define NT 2048
#define ND 2048
#define NH 16
#define NKV 4
#define HD 128

typedef __half f16;

// ---------------- scratch -----------------------------------------------------
static __device__ float g_cos[NT * 64];
static __device__ float g_sin[NT * 64];
static __device__ f16 g_xh[(size_t)NB * NT * ND];
static __device__ f16 g_wh[(size_t)3072 * 2048];          // [wq;wk;wv] hi
static __device__ f16 g_woh[(size_t)2048 * 2048];
static __device__ f16 g_yh[(size_t)NB * NT * ND];
static __device__ f16 g_Qh[(size_t)NB * NH * NT * HD];    // pre-scaled by log2e/sqrt(128)
static __device__ f16 g_Kh[(size_t)NB * NKV * NT * HD];
static __device__ f16 g_Vh[(size_t)NB * NKV * NT * HD];

// ---------------- PTX helpers (sm_80-compatible) ------------------------------
__device__ __forceinline__ uint32_t smem_u32(const void* p) {
    uint32_t a;
    asm("{ .reg .u64 t; cvta.to.shared.u64 t, %1; cvt.u32.u64 %0, t; }" : "=r"(a) : "l"(p));
    return a;
}
#define CP_ASYNC16(dst, src)                                                   \
    asm volatile("cp.async.cg.shared.global [%0], [%1], 16;"                   \
                 :: "r"(dst), "l"(src) : "memory")
#define CP_COMMIT() asm volatile("cp.async.commit_group;" ::: "memory")
#define CP_WAIT0()  asm volatile("cp.async.wait_group 0;" ::: "memory")
#define CP_WAIT1()  asm volatile("cp.async.wait_group 1;" ::: "memory")
#define LDSM_X4(r0, r1, r2, r3, addr)                                          \
    asm volatile("ldmatrix.sync.aligned.m8n8.x4.shared.b16 {%0,%1,%2,%3}, [%4];" \
                 : "=r"(r0), "=r"(r1), "=r"(r2), "=r"(r3) : "r"(addr))
#define LDSM_X4_T(r0, r1, r2, r3, addr)                                        \
    asm volatile("ldmatrix.sync.aligned.m8n8.x4.trans.shared.b16 {%0,%1,%2,%3}, [%4];" \
                 : "=r"(r0), "=r"(r1), "=r"(r2), "=r"(r3) : "r"(addr))
#define MMA16816(d, a0, a1, a2, a3, b0, b1)                                    \
    asm volatile("mma.sync.aligned.m16n8k16.row.col.f32.f16.f16.f32 "          \
                 "{%0,%1,%2,%3}, {%4,%5,%6,%7}, {%8,%9}, {%0,%1,%2,%3};"       \
                 : "+f"((d)[0]), "+f"((d)[1]), "+f"((d)[2]), "+f"((d)[3])      \
                 : "r"(a0), "r"(a1), "r"(a2), "r"(a3), "r"(b0), "r"(b1))
#define EX2F(d, x) asm("ex2.approx.f32 %0, %1;" : "=f"(d) : "f"(x))

__device__ __forceinline__ uint32_t pack_f16(float a, float b) {
    __half2 t = __floats2half2_rn(a, b);
    return *(uint32_t*)&t;
}

// ---------------- prep: fp32 -> fp16 convert (MLP-4) + RoPE table -------------
__global__ __launch_bounds__(256) void prep_kernel(const float* __restrict__ x,
                                                   const float* __restrict__ wq,
                                                   const float* __restrict__ wk,
                                                   const float* __restrict__ wv,
                                                   const float* __restrict__ wo) {
    int bid = blockIdx.x;
    if (bid >= 4608) {
        int idx = (bid - 4608) * 256 + threadIdx.x;   // t*64 + i
        int ii = idx & 63;
        int t = idx >> 6;
        double f = exp(-((double)(2 * ii) / 128.0) * log(10000.0));
        double a = (double)t * f;
        g_cos[idx] = (float)cos(a);
        g_sin[idx] = (float)sin(a);
        return;
    }
    size_t i = ((size_t)bid * 256 + threadIdx.x) * 16;
    const float* src;
    f16* H;
    if (i < 8388608)        { src = x  + i;            H = g_xh + i; }
    else if (i < 12582912)  { size_t o = i - 8388608;  src = wq + o; H = g_wh + o; }
    else if (i < 13631488)  { size_t o = i - 12582912; src = wk + o; H = g_wh + 4194304 + o; }
    else if (i < 14680064)  { size_t o = i - 13631488; src = wv + o; H = g_wh + 5242880 + o; }
    else                    { size_t o = i - 14680064; src = wo + o; H = g_woh + o; }

    float4 v0 = *(const float4*)(src);
    float4 v1 = *(const float4*)(src + 4);
    float4 v2 = *(const float4*)(src + 8);
    float4 v3 = *(const float4*)(src + 12);
    uint4 o0, o1;
    o0.x = pack_f16(v0.x, v0.y); o0.y = pack_f16(v0.z, v0.w);
    o0.z = pack_f16(v1.x, v1.y); o0.w = pack_f16(v1.z, v1.w);
    o1.x = pack_f16(v2.x, v2.y); o1.y = pack_f16(v2.z, v2.w);
    o1.z = pack_f16(v3.x, v3.y); o1.w = pack_f16(v3.z, v3.w);
    *(uint4*)(H)     = o0;
    *(uint4*)(H + 8) = o1;
}

// ---------------- 1-term fp16 GEMM: CTA 128x256, 512 thr, 3 stages x 2 chunks -
// MODE 0: QKV with fused RoPE+RMSNorm+transpose epilogue -> g_Qh/g_Kh/g_Vh
// MODE 1: WO, plain fp32 epilogue -> C
#define GEMM_SMEM (3 * 61440)
template <int MODE>
__global__ __launch_bounds__(512) void gemm_mma_kernel(const f16* __restrict__ Ah,
                                                       const f16* __restrict__ Bh,
                                                       float* __restrict__ C,
                                                       const float* __restrict__ qnw,
                                                       const float* __restrict__ knw) {
    extern __shared__ char smem[];
    uint32_t sb = smem_u32(smem);
    int tid = threadIdx.x, lane = tid & 31, wid = tid >> 5;
    int wm = wid & 3, wn = wid >> 2;   // 4 M-warps x 4 N-warps
    int m0 = blockIdx.x * 128, n0 = blockIdx.y * 256;

    int arow = tid >> 2, q4 = tid & 3;
    size_t aoff0 = (size_t)(m0 + arow) * 2048 + q4 * 8;
    size_t boff0 = (size_t)(n0 + arow) * 2048 + q4 * 8;
    size_t boff1 = (size_t)(n0 + 128 + arow) * 2048 + q4 * 8;
    uint32_t adst  = sb + arow * 80 + q4 * 16;
    uint32_t bdst0 = sb + 10240 + arow * 80 + q4 * 16;
    uint32_t bdst1 = sb + 10240 + (128 + arow) * 80 + q4 * 16;

    float acc[2][8][4];
#pragma unroll
    for (int mi = 0; mi < 2; mi++)
#pragma unroll
        for (int t = 0; t < 8; t++)
#pragma unroll
            for (int c = 0; c < 4; c++) acc[mi][t][c] = 0.f;

#define GEMM_PREFETCH(st, bsel) do {                                           \
    uint32_t off = (bsel) * 61440;                                             \
    size_t ko = (size_t)(st) * 64;                                             \
    CP_ASYNC16(adst + off,          (const void*)(Ah + aoff0 + ko));           \
    CP_ASYNC16(adst + off + 30720,  (const void*)(Ah + aoff0 + ko + 32));      \
    CP_ASYNC16(bdst0 + off,         (const void*)(Bh + boff0 + ko));           \
    CP_ASYNC16(bdst0 + off + 30720, (const void*)(Bh + boff0 + ko + 32));      \
    CP_ASYNC16(bdst1 + off,         (const void*)(Bh + boff1 + ko));           \
    CP_ASYNC16(bdst1 + off + 30720, (const void*)(Bh + boff1 + ko + 32));      \
} while (0)

    GEMM_PREFETCH(0, 0);
    CP_COMMIT();
    GEMM_PREFETCH(1, 1);
    CP_COMMIT();

    int r16 = lane & 15;
    uint32_t cby = (lane >> 4) * 16;

    for (int st = 0; st < 32; st++) {
        CP_WAIT1();
        __syncthreads();
        if (st < 30) { GEMM_PREFETCH(st + 2, (st + 2) % 3); CP_COMMIT(); }
        uint32_t base = sb + (st % 3) * 61440;
#pragma unroll
        for (int sub = 0; sub < 2; sub++) {
            uint32_t cb = base + sub * 30720;
#pragma unroll
            for (int ks = 0; ks < 2; ks++) {
                uint32_t ahf[2][4], bhf[4][4];
#pragma unroll
                for (int mi = 0; mi < 2; mi++) {
                    uint32_t ad = cb + ((wm * 32 + mi * 16 + r16) * 40 + ks * 16) * 2 + cby;
                    LDSM_X4(ahf[mi][0], ahf[mi][1], ahf[mi][2], ahf[mi][3], ad);
                }
#pragma unroll
                for (int g = 0; g < 4; g++) {
                    uint32_t bd = cb + 10240 + ((wn * 64 + g * 16 + r16) * 40 + ks * 16) * 2 + cby;
                    LDSM_X4(bhf[g][0], bhf[g][1], bhf[g][2], bhf[g][3], bd);
                }
#pragma unroll
                for (int mi = 0; mi < 2; mi++)
#pragma unroll
                    for (int t = 0; t < 8; t++) {
                        int g = t >> 1, s = t & 1;
                        MMA16816(acc[mi][t], ahf[mi][0], ahf[mi][1], ahf[mi][2], ahf[mi][3],
                                 bhf[g][s], bhf[g][s + 2]);
                    }
            }
        }
        __syncthreads();
    }

    if (MODE == 1) {
        // plain fp32 epilogue (WO -> final output)
#pragma unroll
        for (int mi = 0; mi < 2; mi++)
#pragma unroll
            for (int t = 0; t < 8; t++) {
                int r = m0 + wm * 32 + mi * 16 + (lane >> 2);
                int cc = n0 + wn * 64 + t * 8 + (lane & 3) * 2;
                *(float2*)&C[(size_t)r * 2048 + cc]       = make_float2(acc[mi][t][0], acc[mi][t][1]);
                *(float2*)&C[(size_t)(r + 8) * 2048 + cc] = make_float2(acc[mi][t][2], acc[mi][t][3]);
            }
        return;
    }

    // ---------------- fused RoPE + RMSNorm + transpose epilogue ----------------
    int cc0 = n0 + wn * 64;          // warp's column base; one head per warp
    bool isQ = cc0 < 2048;
    bool isK = (cc0 >= 2048) && (cc0 < 2560);
    bool isV = cc0 >= 2560;

    // per-row sum of squares over this warp's 64 cols (pre-RoPE: rotation-invariant)
    float ss[2][2] = {{0.f, 0.f}, {0.f, 0.f}};
    if (!isV) {
#pragma unroll
        for (int mi = 0; mi < 2; mi++)
#pragma unroll
            for (int t = 0; t < 8; t++) {
                ss[mi][0] = fmaf(acc[mi][t][0], acc[mi][t][0],
                            fmaf(acc[mi][t][1], acc[mi][t][1], ss[mi][0]));
                ss[mi][1] = fmaf(acc[mi][t][2], acc[mi][t][2],
                            fmaf(acc[mi][t][3], acc[mi][t][3], ss[mi][1]));
            }
#pragma unroll
        for (int mi = 0; mi < 2; mi++)
#pragma unroll
            for (int rh = 0; rh < 2; rh++) {
                ss[mi][rh] += __shfl_xor_sync(0xffffffffu, ss[mi][rh], 1);
                ss[mi][rh] += __shfl_xor_sync(0xffffffffu, ss[mi][rh], 2);
            }
    }
    float* red = (float*)smem;       // [4 wn][128 rows]
    if ((lane & 3) == 0) {
#pragma unroll
        for (int mi = 0; mi < 2; mi++) {
            int lr0 = wm * 32 + mi * 16 + (lane >> 2);
            red[wn * 128 + lr0]     = ss[mi][0];
            red[wn * 128 + lr0 + 8] = ss[mi][1];
        }
    }
    __syncthreads();

    float rs[2][2];
    float sc = isQ ? 0.12752573683985877f : 1.0f;   // log2(e)/sqrt(128) folded into q
    if (!isV) {
#pragma unroll
        for (int mi = 0; mi < 2; mi++)
#pragma unroll
            for (int rh = 0; rh < 2; rh++) {
                int lr = wm * 32 + mi * 16 + (lane >> 2) + rh * 8;
                float full = ss[mi][rh] + red[(wn ^ 1) * 128 + lr];
                rs[mi][rh] = rsqrtf(full * (1.0f / 128.0f) + 1.1920929e-7f) * sc;
            }
    }

    f16* dst;
    int head, nheads;
    const float* nw = nullptr;
    if (isQ)      { head = cc0 >> 7;          nheads = NH;  dst = g_Qh; nw = qnw; }
    else if (isK) { head = (cc0 - 2048) >> 7; nheads = NKV; dst = g_Kh; nw = knw; }
    else          { head = (cc0 - 2560) >> 7; nheads = NKV; dst = g_Vh; }

#pragma unroll
    for (int t = 0; t < 8; t++) {
        int d0 = (cc0 & 127) + t * 8 + (lane & 3) * 2;
        float w0 = 1.f, w1 = 1.f;
        if (!isV) {
            float2 wv = *(const float2*)(nw + d0);
            w0 = wv.x; w1 = wv.y;
        }
#pragma unroll
        for (int mi = 0; mi < 2; mi++) {
            int r = m0 + wm * 32 + mi * 16 + (lane >> 2);
#pragma unroll
            for (int rh = 0; rh < 2; rh++) {
                int rr = r + rh * 8;
                int tt = rr & (NT - 1);
                int bb = rr >> 11;
                float a0 = acc[mi][t][rh * 2], a1 = acc[mi][t][rh * 2 + 1];
                size_t idx = (((size_t)(bb * nheads + head)) * NT + tt) * HD + d0;
                if (isV) {
                    *(uint32_t*)&dst[idx] = pack_f16(a0, a1);
                } else {
                    float cth = g_cos[tt * 64 + (d0 >> 1)];
                    float sth = g_sin[tt * 64 + (d0 >> 1)];
                    float o0 = a0 * cth - a1 * sth;
                    float o1 = a0 * sth + a1 * cth;
                    float r2 = rs[mi][rh];
                    *(uint32_t*)&dst[idx] = pack_f16(o0 * r2 * w0, o1 * r2 * w1);
                }
            }
        }
    }
}

// ---------------- flash attention: 4 warps x 32 Q rows, scalar l --------------
#define FROW 272
#define QTILE (128 * FROW)     // 34816
#define KVTILE (64 * FROW)     // 17408
#define FLASH_SMEM (QTILE + 4 * KVTILE)   // 104448
#define C2LOG2E 2.8853900817779268f

__global__ __launch_bounds__(128, 2) void flash_kernel() {
    extern __shared__ char smem[];
    uint32_t sb = smem_u32(smem);

    int qt = 15 - (int)blockIdx.x;       // long causal rows first
    int h = blockIdx.y, b = blockIdx.z;
    int kvh = h >> 2;
    int tid = threadIdx.x, lane = tid & 31, w = tid >> 5;

    const f16* Qhg = g_Qh + ((size_t)(b * NH + h) * NT + qt * 128) * HD;
    const f16* Khg = g_Kh + (size_t)(b * NKV + kvh) * NT * HD;
    const f16* Vhg = g_Vh + (size_t)(b * NKV + kvh) * NT * HD;

    // Q: 128 rows x 256B
#pragma unroll
    for (int i = 0; i < 8; i++) {
        int linear = i * 128 + tid;
        int r = linear >> 3, c = linear & 7;
        uint32_t d = sb + r * FROW + c * 32;
        CP_ASYNC16(d,      (const void*)(Qhg + r * HD + c * 16));
        CP_ASYNC16(d + 16, (const void*)(Qhg + r * HD + c * 16 + 8));
    }
    CP_COMMIT();

#define LOAD_KV(kt, buf) do {                                                  \
    uint32_t kb_ = sb + QTILE + (buf) * (2 * KVTILE);                          \
    _Pragma("unroll")                                                          \
    for (int i_ = 0; i_ < 4; i_++) {                                           \
        int lin_ = i_ * 128 + tid;                                             \
        int r_ = lin_ >> 3, c_ = lin_ & 7;                                     \
        size_t go_ = (size_t)((kt) * 64 + r_) * HD + c_ * 16;                  \
        uint32_t o_ = r_ * FROW + c_ * 32;                                     \
        CP_ASYNC16(kb_ + o_,                (const void*)(Khg + go_));         \
        CP_ASYNC16(kb_ + o_ + 16,           (const void*)(Khg + go_ + 8));     \
        CP_ASYNC16(kb_ + KVTILE + o_,       (const void*)(Vhg + go_));         \
        CP_ASYNC16(kb_ + KVTILE + o_ + 16,  (const void*)(Vhg + go_ + 8));     \
    }                                                                          \
} while (0)

    LOAD_KV(0, 0);
    CP_COMMIT();

    float acc[2][16][4];
#pragma unroll
    for (int mi = 0; mi < 2; mi++)
#pragma unroll
        for (int t = 0; t < 16; t++)
#pragma unroll
            for (int c = 0; c < 4; c++) acc[mi][t][c] = 0.f;
    float lr[2][2] = {{0.f, 0.f}, {0.f, 0.f}};

    int r16 = lane & 15;
    uint32_t cby = (lane >> 4) * 16;
    int qrow0 = qt * 128 + w * 32 + (lane >> 2);
    int nkt = 2 * qt + 2;

    for (int kt = 0; kt < nkt; kt++) {
        if (kt > 0) __syncthreads();
        if (kt + 1 < nkt) {
            LOAD_KV(kt + 1, (kt + 1) & 1);
            CP_COMMIT();
            CP_WAIT1();
        } else {
            CP_WAIT0();
        }
        __syncthreads();

        uint32_t kb = sb + QTILE + (kt & 1) * (2 * KVTILE);
        uint32_t vb = kb + KVTILE;

        // ---- S = Q K^T (32 rows/warp) ----
        float s[2][8][4];
#pragma unroll
        for (int mi = 0; mi < 2; mi++)
#pragma unroll
            for (int t = 0; t < 8; t++)
#pragma unroll
                for (int c = 0; c < 4; c++) s[mi][t][c] = 0.f;
#pragma unroll
        for (int ks = 0; ks < 8; ks++) {
            uint32_t qh2[2][4], kh[4][4];
#pragma unroll
            for (int mi = 0; mi < 2; mi++) {
                uint32_t qa = sb + (w * 32 + mi * 16 + r16) * FROW + ks * 32 + cby;
                LDSM_X4(qh2[mi][0], qh2[mi][1], qh2[mi][2], qh2[mi][3], qa);
            }
#pragma unroll
            for (int g = 0; g < 4; g++) {
                uint32_t ka = kb + (g * 16 + r16) * FROW + ks * 32 + cby;
                LDSM_X4(kh[g][0], kh[g][1], kh[g][2], kh[g][3], ka);
            }
#pragma unroll
            for (int mi = 0; mi < 2; mi++)
#pragma unroll
                for (int t = 0; t < 8; t++) {
                    int g = t >> 1, sel = t & 1;
                    MMA16816(s[mi][t], qh2[mi][0], qh2[mi][1], qh2[mi][2], qh2[mi][3],
                             kh[g][sel], kh[g][sel + 2]);
                }
        }

        // ---- p = 2^(s - 2*log2e); masked -> 0; l += rounded p --------------
        bool maskt = (kt >= 2 * qt);
        uint32_t ph[2][4][4];
#pragma unroll
        for (int mi = 0; mi < 2; mi++) {
            int row0 = qrow0 + mi * 16;
#pragma unroll
            for (int t = 0; t < 8; t++) {
                if (maskt) {
                    int colb = kt * 64 + t * 8 + (lane & 3) * 2;
                    if (colb     > row0)     s[mi][t][0] = -INFINITY;
                    if (colb + 1 > row0)     s[mi][t][1] = -INFINITY;
                    if (colb     > row0 + 8) s[mi][t][2] = -INFINITY;
                    if (colb + 1 > row0 + 8) s[mi][t][3] = -INFINITY;
                }
                float p0, p1, p2, p3;
                EX2F(p0, s[mi][t][0] - C2LOG2E);
                EX2F(p1, s[mi][t][1] - C2LOG2E);
                EX2F(p2, s[mi][t][2] - C2LOG2E);
                EX2F(p3, s[mi][t][3] - C2LOG2E);
                uint32_t pk01 = pack_f16(p0, p1);
                uint32_t pk23 = pack_f16(p2, p3);
                float2 f01 = __half22float2(*(__half2*)&pk01);
                float2 f23 = __half22float2(*(__half2*)&pk23);
                lr[mi][0] += f01.x + f01.y;
                lr[mi][1] += f23.x + f23.y;
                int j = t >> 1;
                if ((t & 1) == 0) { ph[mi][j][0] = pk01; ph[mi][j][1] = pk23; }
                else              { ph[mi][j][2] = pk01; ph[mi][j][3] = pk23; }
            }
        }

        // ---- O += P V (1 V-LDSM feeds 4 MMAs) ----
#pragma unroll
        for (int j = 0; j < 4; j++) {
#pragma unroll
            for (int g = 0; g < 8; g++) {
                uint32_t va = vb + (j * 16 + r16) * FROW + g * 32 + cby;
                uint32_t vh[4];
                LDSM_X4_T(vh[0], vh[1], vh[2], vh[3], va);
                MMA16816(acc[0][2 * g],     ph[0][j][0], ph[0][j][1], ph[0][j][2], ph[0][j][3], vh[0], vh[1]);
                MMA16816(acc[0][2 * g + 1], ph[0][j][0], ph[0][j][1], ph[0][j][2], ph[0][j][3], vh[2], vh[3]);
                MMA16816(acc[1][2 * g],     ph[1][j][0], ph[1][j][1], ph[1][j][2], ph[1][j][3], vh[0], vh[1]);
                MMA16816(acc[1][2 * g + 1], ph[1][j][0], ph[1][j][1], ph[1][j][2], ph[1][j][3], vh[2], vh[3]);
            }
        }
    }

    // ---- reduce l, normalize, write ----
#pragma unroll
    for (int mi = 0; mi < 2; mi++) {
#pragma unroll
        for (int jj = 0; jj < 2; jj++) {
            lr[mi][jj] += __shfl_xor_sync(0xffffffffu, lr[mi][jj], 1);
            lr[mi][jj] += __shfl_xor_sync(0xffffffffu, lr[mi][jj], 2);
        }
        float inv0 = 1.0f / lr[mi][0], inv1 = 1.0f / lr[mi][1];
        int grow0 = b * NT + qt * 128 + w * 32 + mi * 16 + (lane >> 2);
#pragma unroll
        for (int t = 0; t < 16; t++) {
            int col = h * 128 + t * 8 + (lane & 3) * 2;
            size_t i0 = (size_t)grow0 * ND + col;
            size_t i1 = (size_t)(grow0 + 8) * ND + col;
            *(uint32_t*)&g_yh[i0] = pack_f16(acc[mi][t][0] * inv0, acc[mi][t][1] * inv0);
            *(uint32_t*)&g_yh[i1] = pack_f16(acc[mi][t][2] * inv1, acc[mi][t][3] * inv1);
        }
    }
}

// ---------------- launch ------------------------------------------------------
extern "C" void kernel_launch(void* const* d_in, const int* in_sizes, int n_in,
                              void* d_out, int out_size) {
    const float* x   = (const float*)d_in[0];
    const float* wq  = (const float*)d_in[1];
    const float* wk  = (const float*)d_in[2];
    const float* wv  = (const float*)d_in[3];
    const float* wo  = (const float*)d_in[4];
    const float* qnw = (const float*)d_in[5];
    const float* knw = (const float*)d_in[6];
    float* out = (float*)d_out;

    cudaFuncSetAttribute(flash_kernel, cudaFuncAttributeMaxDynamicSharedMemorySize,
                         FLASH_SMEM);
    cudaFuncSetAttribute(gemm_mma_kernel<0>, cudaFuncAttributeMaxDynamicSharedMemorySize,
                         GEMM_SMEM);
    cudaFuncSetAttribute(gemm_mma_kernel<1>, cudaFuncAttributeMaxDynamicSharedMemorySize,
                         GEMM_SMEM);

    f16* xh_ptr;      cudaGetSymbolAddress((void**)&xh_ptr, g_xh);
    f16* wh_ptr;      cudaGetSymbolAddress((void**)&wh_ptr, g_wh);
    f16* woh_ptr;     cudaGetSymbolAddress((void**)&woh_ptr, g_woh);
    f16* yh_ptr;      cudaGetSymbolAddress((void**)&yh_ptr, g_yh);

    prep_kernel<<<5120, 256>>>(x, wq, wk, wv, wo);
    gemm_mma_kernel<0><<<dim3(32, 12), 512, GEMM_SMEM>>>(xh_ptr, wh_ptr, nullptr, qnw, knw);
    flash_kernel<<<dim3(16, NH, NB), 128, FLASH_SMEM>>>();
    gemm_mma_kernel<1><<<dim3(32, 8), 512, GEMM_SMEM>>>(yh_ptr, woh_ptr, out, nullptr, nullptr);
}

// round 17
// speedup vs baseline: 1.0018x; 1.0018x over previous
#include <cuda_runtime.h>
#include <cuda_fp16.h>
#include <math.h>
#include <cstdint>

#define NB 2
#define NT 2048
#define ND 2048
#define NH 16
#define NKV 4
#define HD 128

typedef __half f16;

// ---------------- scratch -----------------------------------------------------
static __device__ float g_cos[NT * 64];
static __device__ float g_sin[NT * 64];
static __device__ f16 g_xh[(size_t)NB * NT * ND];
static __device__ f16 g_wh[(size_t)3072 * 2048];          // [wq;wk;wv] hi
static __device__ f16 g_woh[(size_t)2048 * 2048];
static __device__ f16 g_yh[(size_t)NB * NT * ND];
static __device__ f16 g_Qh[(size_t)NB * NH * NT * HD];    // pre-scaled by log2e/sqrt(128)
static __device__ f16 g_Kh[(size_t)NB * NKV * NT * HD];
static __device__ f16 g_Vh[(size_t)NB * NKV * NT * HD];

// ---------------- PTX helpers (sm_80-compatible) ------------------------------
__device__ __forceinline__ uint32_t smem_u32(const void* p) {
    uint32_t a;
    asm("{ .reg .u64 t; cvta.to.shared.u64 t, %1; cvt.u32.u64 %0, t; }" : "=r"(a) : "l"(p));
    return a;
}
#define CP_ASYNC16(dst, src)                                                   \
    asm volatile("cp.async.cg.shared.global [%0], [%1], 16;"                   \
                 :: "r"(dst), "l"(src) : "memory")
#define CP_COMMIT() asm volatile("cp.async.commit_group;" ::: "memory")
#define CP_WAIT0()  asm volatile("cp.async.wait_group 0;" ::: "memory")
#define CP_WAIT1()  asm volatile("cp.async.wait_group 1;" ::: "memory")
#define LDSM_X4(r0, r1, r2, r3, addr)                                          \
    asm volatile("ldmatrix.sync.aligned.m8n8.x4.shared.b16 {%0,%1,%2,%3}, [%4];" \
                 : "=r"(r0), "=r"(r1), "=r"(r2), "=r"(r3) : "r"(addr))
#define LDSM_X4_T(r0, r1, r2, r3, addr)                                        \
    asm volatile("ldmatrix.sync.aligned.m8n8.x4.trans.shared.b16 {%0,%1,%2,%3}, [%4];" \
                 : "=r"(r0), "=r"(r1), "=r"(r2), "=r"(r3) : "r"(addr))
#define MMA16816(d, a0, a1, a2, a3, b0, b1)                                    \
    asm volatile("mma.sync.aligned.m16n8k16.row.col.f32.f16.f16.f32 "          \
                 "{%0,%1,%2,%3}, {%4,%5,%6,%7}, {%8,%9}, {%0,%1,%2,%3};"       \
                 : "+f"((d)[0]), "+f"((d)[1]), "+f"((d)[2]), "+f"((d)[3])      \
                 : "r"(a0), "r"(a1), "r"(a2), "r"(a3), "r"(b0), "r"(b1))
#define EX2_H2(d, x) asm("ex2.approx.f16x2 %0, %1;" : "=r"(d) : "r"(x))

__device__ __forceinline__ uint32_t pack_f16(float a, float b) {
    __half2 t = __floats2half2_rn(a, b);
    return *(uint32_t*)&t;
}

// ---------------- prep: fp32 -> fp16 convert (MLP-4) + RoPE table -------------
__global__ __launch_bounds__(256) void prep_kernel(const float* __restrict__ x,
                                                   const float* __restrict__ wq,
                                                   const float* __restrict__ wk,
                                                   const float* __restrict__ wv,
                                                   const float* __restrict__ wo) {
    int bid = blockIdx.x;
    if (bid >= 4608) {
        int idx = (bid - 4608) * 256 + threadIdx.x;   // t*64 + i
        int ii = idx & 63;
        int t = idx >> 6;
        double f = exp(-((double)(2 * ii) / 128.0) * log(10000.0));
        double a = (double)t * f;
        g_cos[idx] = (float)cos(a);
        g_sin[idx] = (float)sin(a);
        return;
    }
    size_t i = ((size_t)bid * 256 + threadIdx.x) * 16;
    const float* src;
    f16* H;
    if (i < 8388608)        { src = x  + i;            H = g_xh + i; }
    else if (i < 12582912)  { size_t o = i - 8388608;  src = wq + o; H = g_wh + o; }
    else if (i < 13631488)  { size_t o = i - 12582912; src = wk + o; H = g_wh + 4194304 + o; }
    else if (i < 14680064)  { size_t o = i - 13631488; src = wv + o; H = g_wh + 5242880 + o; }
    else                    { size_t o = i - 14680064; src = wo + o; H = g_woh + o; }

    float4 v0 = *(const float4*)(src);
    float4 v1 = *(const float4*)(src + 4);
    float4 v2 = *(const float4*)(src + 8);
    float4 v3 = *(const float4*)(src + 12);
    uint4 o0, o1;
    o0.x = pack_f16(v0.x, v0.y); o0.y = pack_f16(v0.z, v0.w);
    o0.z = pack_f16(v1.x, v1.y); o0.w = pack_f16(v1.z, v1.w);
    o1.x = pack_f16(v2.x, v2.y); o1.y = pack_f16(v2.z, v2.w);
    o1.z = pack_f16(v3.x, v3.y); o1.w = pack_f16(v3.z, v3.w);
    *(uint4*)(H)     = o0;
    *(uint4*)(H + 8) = o1;
}

// ---------------- 1-term fp16 GEMM: CTA 128x256, 512 thr, 3 stages x 2 chunks -
// MODE 0: QKV with fused RoPE+RMSNorm+transpose epilogue -> g_Qh/g_Kh/g_Vh
// MODE 1: WO, plain fp32 epilogue -> C
#define GEMM_SMEM (3 * 61440)
template <int MODE>
__global__ __launch_bounds__(512) void gemm_mma_kernel(const f16* __restrict__ Ah,
                                                       const f16* __restrict__ Bh,
                                                       float* __restrict__ C,
                                                       const float* __restrict__ qnw,
                                                       const float* __restrict__ knw) {
    extern __shared__ char smem[];
    uint32_t sb = smem_u32(smem);
    int tid = threadIdx.x, lane = tid & 31, wid = tid >> 5;
    int wm = wid & 3, wn = wid >> 2;   // 4 M-warps x 4 N-warps
    int m0 = blockIdx.x * 128, n0 = blockIdx.y * 256;

    int arow = tid >> 2, q4 = tid & 3;
    size_t aoff0 = (size_t)(m0 + arow) * 2048 + q4 * 8;
    size_t boff0 = (size_t)(n0 + arow) * 2048 + q4 * 8;
    size_t boff1 = (size_t)(n0 + 128 + arow) * 2048 + q4 * 8;
    uint32_t adst  = sb + arow * 80 + q4 * 16;
    uint32_t bdst0 = sb + 10240 + arow * 80 + q4 * 16;
    uint32_t bdst1 = sb + 10240 + (128 + arow) * 80 + q4 * 16;

    float acc[2][8][4];
#pragma unroll
    for (int mi = 0; mi < 2; mi++)
#pragma unroll
        for (int t = 0; t < 8; t++)
#pragma unroll
            for (int c = 0; c < 4; c++) acc[mi][t][c] = 0.f;

#define GEMM_PREFETCH(st, bsel) do {                                           \
    uint32_t off = (bsel) * 61440;                                             \
    size_t ko = (size_t)(st) * 64;                                             \
    CP_ASYNC16(adst + off,          (const void*)(Ah + aoff0 + ko));           \
    CP_ASYNC16(adst + off + 30720,  (const void*)(Ah + aoff0 + ko + 32));      \
    CP_ASYNC16(bdst0 + off,         (const void*)(Bh + boff0 + ko));           \
    CP_ASYNC16(bdst0 + off + 30720, (const void*)(Bh + boff0 + ko + 32));      \
    CP_ASYNC16(bdst1 + off,         (const void*)(Bh + boff1 + ko));           \
    CP_ASYNC16(bdst1 + off + 30720, (const void*)(Bh + boff1 + ko + 32));      \
} while (0)

    GEMM_PREFETCH(0, 0);
    CP_COMMIT();
    GEMM_PREFETCH(1, 1);
    CP_COMMIT();

    int r16 = lane & 15;
    uint32_t cby = (lane >> 4) * 16;

    for (int st = 0; st < 32; st++) {
        CP_WAIT1();
        __syncthreads();
        if (st < 30) { GEMM_PREFETCH(st + 2, (st + 2) % 3); CP_COMMIT(); }
        uint32_t base = sb + (st % 3) * 61440;
#pragma unroll
        for (int sub = 0; sub < 2; sub++) {
            uint32_t cb = base + sub * 30720;
#pragma unroll
            for (int ks = 0; ks < 2; ks++) {
                uint32_t ahf[2][4], bhf[4][4];
#pragma unroll
                for (int mi = 0; mi < 2; mi++) {
                    uint32_t ad = cb + ((wm * 32 + mi * 16 + r16) * 40 + ks * 16) * 2 + cby;
                    LDSM_X4(ahf[mi][0], ahf[mi][1], ahf[mi][2], ahf[mi][3], ad);
                }
#pragma unroll
                for (int g = 0; g < 4; g++) {
                    uint32_t bd = cb + 10240 + ((wn * 64 + g * 16 + r16) * 40 + ks * 16) * 2 + cby;
                    LDSM_X4(bhf[g][0], bhf[g][1], bhf[g][2], bhf[g][3], bd);
                }
#pragma unroll
                for (int mi = 0; mi < 2; mi++)
#pragma unroll
                    for (int t = 0; t < 8; t++) {
                        int g = t >> 1, s = t & 1;
                        MMA16816(acc[mi][t], ahf[mi][0], ahf[mi][1], ahf[mi][2], ahf[mi][3],
                                 bhf[g][s], bhf[g][s + 2]);
                    }
            }
        }
        __syncthreads();
    }

    if (MODE == 1) {
#pragma unroll
        for (int mi = 0; mi < 2; mi++)
#pragma unroll
            for (int t = 0; t < 8; t++) {
                int r = m0 + wm * 32 + mi * 16 + (lane >> 2);
                int cc = n0 + wn * 64 + t * 8 + (lane & 3) * 2;
                *(float2*)&C[(size_t)r * 2048 + cc]       = make_float2(acc[mi][t][0], acc[mi][t][1]);
                *(float2*)&C[(size_t)(r + 8) * 2048 + cc] = make_float2(acc[mi][t][2], acc[mi][t][3]);
            }
        return;
    }

    // ---------------- fused RoPE + RMSNorm + transpose epilogue ----------------
    int cc0 = n0 + wn * 64;          // warp's column base; one head per warp
    bool isQ = cc0 < 2048;
    bool isK = (cc0 >= 2048) && (cc0 < 2560);
    bool isV = cc0 >= 2560;

    float ss[2][2] = {{0.f, 0.f}, {0.f, 0.f}};
    if (!isV) {
#pragma unroll
        for (int mi = 0; mi < 2; mi++)
#pragma unroll
            for (int t = 0; t < 8; t++) {
                ss[mi][0] = fmaf(acc[mi][t][0], acc[mi][t][0],
                            fmaf(acc[mi][t][1], acc[mi][t][1], ss[mi][0]));
                ss[mi][1] = fmaf(acc[mi][t][2], acc[mi][t][2],
                            fmaf(acc[mi][t][3], acc[mi][t][3], ss[mi][1]));
            }
#pragma unroll
        for (int mi = 0; mi < 2; mi++)
#pragma unroll
            for (int rh = 0; rh < 2; rh++) {
                ss[mi][rh] += __shfl_xor_sync(0xffffffffu, ss[mi][rh], 1);
                ss[mi][rh] += __shfl_xor_sync(0xffffffffu, ss[mi][rh], 2);
            }
    }
    float* red = (float*)smem;       // [4 wn][128 rows]
    if ((lane & 3) == 0) {
#pragma unroll
        for (int mi = 0; mi < 2; mi++) {
            int lr0 = wm * 32 + mi * 16 + (lane >> 2);
            red[wn * 128 + lr0]     = ss[mi][0];
            red[wn * 128 + lr0 + 8] = ss[mi][1];
        }
    }
    __syncthreads();

    float rs[2][2];
    float sc = isQ ? 0.12752573683985877f : 1.0f;   // log2(e)/sqrt(128) folded into q
    if (!isV) {
#pragma unroll
        for (int mi = 0; mi < 2; mi++)
#pragma unroll
            for (int rh = 0; rh < 2; rh++) {
                int lr = wm * 32 + mi * 16 + (lane >> 2) + rh * 8;
                float full = ss[mi][rh] + red[(wn ^ 1) * 128 + lr];
                rs[mi][rh] = rsqrtf(full * (1.0f / 128.0f) + 1.1920929e-7f) * sc;
            }
    }

    f16* dst;
    int head, nheads;
    const float* nw = nullptr;
    if (isQ)      { head = cc0 >> 7;          nheads = NH;  dst = g_Qh; nw = qnw; }
    else if (isK) { head = (cc0 - 2048) >> 7; nheads = NKV; dst = g_Kh; nw = knw; }
    else          { head = (cc0 - 2560) >> 7; nheads = NKV; dst = g_Vh; }

#pragma unroll
    for (int t = 0; t < 8; t++) {
        int d0 = (cc0 & 127) + t * 8 + (lane & 3) * 2;
        float w0 = 1.f, w1 = 1.f;
        if (!isV) {
            float2 wv = *(const float2*)(nw + d0);
            w0 = wv.x; w1 = wv.y;
        }
#pragma unroll
        for (int mi = 0; mi < 2; mi++) {
            int r = m0 + wm * 32 + mi * 16 + (lane >> 2);
#pragma unroll
            for (int rh = 0; rh < 2; rh++) {
                int rr = r + rh * 8;
                int tt = rr & (NT - 1);
                int bb = rr >> 11;
                float a0 = acc[mi][t][rh * 2], a1 = acc[mi][t][rh * 2 + 1];
                size_t idx = (((size_t)(bb * nheads + head)) * NT + tt) * HD + d0;
                if (isV) {
                    *(uint32_t*)&dst[idx] = pack_f16(a0, a1);
                } else {
                    float cth = g_cos[tt * 64 + (d0 >> 1)];
                    float sth = g_sin[tt * 64 + (d0 >> 1)];
                    float o0 = a0 * cth - a1 * sth;
                    float o1 = a0 * sth + a1 * cth;
                    float r2 = rs[mi][rh];
                    *(uint32_t*)&dst[idx] = pack_f16(o0 * r2 * w0, o1 * r2 * w1);
                }
            }
        }
    }
}

// ---------------- flash attention: 4 warps x 32 Q rows, f16x2 ex2 softmax -----
#define FROW 272
#define QTILE (128 * FROW)     // 34816
#define KVTILE (64 * FROW)     // 17408
#define FLASH_SMEM (QTILE + 4 * KVTILE)   // 104448
#define C2LOG2E 2.8853900817779268f

__global__ __launch_bounds__(128, 2) void flash_kernel() {
    extern __shared__ char smem[];
    uint32_t sb = smem_u32(smem);

    int qt = 15 - (int)blockIdx.x;       // long causal rows first
    int h = blockIdx.y, b = blockIdx.z;
    int kvh = h >> 2;
    int tid = threadIdx.x, lane = tid & 31, w = tid >> 5;

    const f16* Qhg = g_Qh + ((size_t)(b * NH + h) * NT + qt * 128) * HD;
    const f16* Khg = g_Kh + (size_t)(b * NKV + kvh) * NT * HD;
    const f16* Vhg = g_Vh + (size_t)(b * NKV + kvh) * NT * HD;

    // Q: 128 rows x 256B
#pragma unroll
    for (int i = 0; i < 8; i++) {
        int linear = i * 128 + tid;
        int r = linear >> 3, c = linear & 7;
        uint32_t d = sb + r * FROW + c * 32;
        CP_ASYNC16(d,      (const void*)(Qhg + r * HD + c * 16));
        CP_ASYNC16(d + 16, (const void*)(Qhg + r * HD + c * 16 + 8));
    }
    CP_COMMIT();

#define LOAD_KV(kt, buf) do {                                                  \
    uint32_t kb_ = sb + QTILE + (buf) * (2 * KVTILE);                          \
    _Pragma("unroll")                                                          \
    for (int i_ = 0; i_ < 4; i_++) {                                           \
        int lin_ = i_ * 128 + tid;                                             \
        int r_ = lin_ >> 3, c_ = lin_ & 7;                                     \
        size_t go_ = (size_t)((kt) * 64 + r_) * HD + c_ * 16;                  \
        uint32_t o_ = r_ * FROW + c_ * 32;                                     \
        CP_ASYNC16(kb_ + o_,                (const void*)(Khg + go_));         \
        CP_ASYNC16(kb_ + o_ + 16,           (const void*)(Khg + go_ + 8));     \
        CP_ASYNC16(kb_ + KVTILE + o_,       (const void*)(Vhg + go_));         \
        CP_ASYNC16(kb_ + KVTILE + o_ + 16,  (const void*)(Vhg + go_ + 8));     \
    }                                                                          \
} while (0)

    LOAD_KV(0, 0);
    CP_COMMIT();

    float acc[2][16][4];
#pragma unroll
    for (int mi = 0; mi < 2; mi++)
#pragma unroll
        for (int t = 0; t < 16; t++)
#pragma unroll
            for (int c = 0; c < 4; c++) acc[mi][t][c] = 0.f;
    float lr[2][2] = {{0.f, 0.f}, {0.f, 0.f}};

    int r16 = lane & 15;
    uint32_t cby = (lane >> 4) * 16;
    int qrow0 = qt * 128 + w * 32 + (lane >> 2);
    int nkt = 2 * qt + 2;

    for (int kt = 0; kt < nkt; kt++) {
        if (kt > 0) __syncthreads();
        if (kt + 1 < nkt) {
            LOAD_KV(kt + 1, (kt + 1) & 1);
            CP_COMMIT();
            CP_WAIT1();
        } else {
            CP_WAIT0();
        }
        __syncthreads();

        uint32_t kb = sb + QTILE + (kt & 1) * (2 * KVTILE);
        uint32_t vb = kb + KVTILE;

        // ---- S = Q K^T (32 rows/warp) ----
        float s[2][8][4];
#pragma unroll
        for (int mi = 0; mi < 2; mi++)
#pragma unroll
            for (int t = 0; t < 8; t++)
#pragma unroll
                for (int c = 0; c < 4; c++) s[mi][t][c] = 0.f;
#pragma unroll
        for (int ks = 0; ks < 8; ks++) {
            uint32_t qh2[2][4], kh[4][4];
#pragma unroll
            for (int mi = 0; mi < 2; mi++) {
                uint32_t qa = sb + (w * 32 + mi * 16 + r16) * FROW + ks * 32 + cby;
                LDSM_X4(qh2[mi][0], qh2[mi][1], qh2[mi][2], qh2[mi][3], qa);
            }
#pragma unroll
            for (int g = 0; g < 4; g++) {
                uint32_t ka = kb + (g * 16 + r16) * FROW + ks * 32 + cby;
                LDSM_X4(kh[g][0], kh[g][1], kh[g][2], kh[g][3], ka);
            }
#pragma unroll
            for (int mi = 0; mi < 2; mi++)
#pragma unroll
                for (int t = 0; t < 8; t++) {
                    int g = t >> 1, sel = t & 1;
                    MMA16816(s[mi][t], qh2[mi][0], qh2[mi][1], qh2[mi][2], qh2[mi][3],
                             kh[g][sel], kh[g][sel + 2]);
                }
        }

        // ---- p = 2^(s - 2*log2e) via f16x2 ex2; masked -> 0; l += rounded p --
        bool maskt = (kt >= 2 * qt);
        uint32_t ph[2][4][4];
#pragma unroll
        for (int mi = 0; mi < 2; mi++) {
            int row0 = qrow0 + mi * 16;
#pragma unroll
            for (int t = 0; t < 8; t++) {
                if (maskt) {
                    int colb = kt * 64 + t * 8 + (lane & 3) * 2;
                    if (colb     > row0)     s[mi][t][0] = -INFINITY;
                    if (colb + 1 > row0)     s[mi][t][1] = -INFINITY;
                    if (colb     > row0 + 8) s[mi][t][2] = -INFINITY;
                    if (colb + 1 > row0 + 8) s[mi][t][3] = -INFINITY;
                }
                uint32_t a01 = pack_f16(s[mi][t][0] - C2LOG2E, s[mi][t][1] - C2LOG2E);
                uint32_t a23 = pack_f16(s[mi][t][2] - C2LOG2E, s[mi][t][3] - C2LOG2E);
                uint32_t pk01, pk23;
                EX2_H2(pk01, a01);
                EX2_H2(pk23, a23);
                float2 f01 = __half22float2(*(__half2*)&pk01);
                float2 f23 = __half22float2(*(__half2*)&pk23);
                lr[mi][0] += f01.x + f01.y;
                lr[mi][1] += f23.x + f23.y;
                int j = t >> 1;
                if ((t & 1) == 0) { ph[mi][j][0] = pk01; ph[mi][j][1] = pk23; }
                else              { ph[mi][j][2] = pk01; ph[mi][j][3] = pk23; }
            }
        }

        // ---- O += P V (1 V-LDSM feeds 4 MMAs) ----
#pragma unroll
        for (int j = 0; j < 4; j++) {
#pragma unroll
            for (int g = 0; g < 8; g++) {
                uint32_t va = vb + (j * 16 + r16) * FROW + g * 32 + cby;
                uint32_t vh[4];
                LDSM_X4_T(vh[0], vh[1], vh[2], vh[3], va);
                MMA16816(acc[0][2 * g],     ph[0][j][0], ph[0][j][1], ph[0][j][2], ph[0][j][3], vh[0], vh[1]);
                MMA16816(acc[0][2 * g + 1], ph[0][j][0], ph[0][j][1], ph[0][j][2], ph[0][j][3], vh[2], vh[3]);
                MMA16816(acc[1][2 * g],     ph[1][j][0], ph[1][j][1], ph[1][j][2], ph[1][j][3], vh[0], vh[1]);
                MMA16816(acc[1][2 * g + 1], ph[1][j][0], ph[1][j][1], ph[1][j][2], ph[1][j][3], vh[2], vh[3]);
            }
        }
    }

    // ---- reduce l, normalize, write ----
#pragma unroll
    for (int mi = 0; mi < 2; mi++) {
#pragma unroll
        for (int jj = 0; jj < 2; jj++) {
            lr[mi][jj] += __shfl_xor_sync(0xffffffffu, lr[mi][jj], 1);
            lr[mi][jj] += __shfl_xor_sync(0xffffffffu, lr[mi][jj], 2);
        }
        float inv0 = 1.0f / lr[mi][0], inv1 = 1.0f / lr[mi][1];
        int grow0 = b * NT + qt * 128 + w * 32 + mi * 16 + (lane >> 2);
#pragma unroll
        for (int t = 0; t < 16; t++) {
            int col = h * 128 + t * 8 + (lane & 3) * 2;
            size_t i0 = (size_t)grow0 * ND + col;
            size_t i1 = (size_t)(grow0 + 8) * ND + col;
            *(uint32_t*)&g_yh[i0] = pack_f16(acc[mi][t][0] * inv0, acc[mi][t][1] * inv0);
            *(uint32_t*)&g_yh[i1] = pack_f16(acc[mi][t][2] * inv1, acc[mi][t][3] * inv1);
        }
    }
}

// ---------------- launch ------------------------------------------------------
extern "C" void kernel_launch(void* const* d_in, const int* in_sizes, int n_in,
                              void* d_out, int out_size) {
    const float* x   = (const float*)d_in[0];
    const float* wq  = (const float*)d_in[1];
    const float* wk  = (const float*)d_in[2];
    const float* wv  = (const float*)d_in[3];
    const float* wo  = (const float*)d_in[4];
    const float* qnw = (const float*)d_in[5];
    const float* knw = (const float*)d_in[6];
    float* out = (float*)d_out;

    cudaFuncSetAttribute(flash_kernel, cudaFuncAttributeMaxDynamicSharedMemorySize,
                         FLASH_SMEM);
    cudaFuncSetAttribute(gemm_mma_kernel<0>, cudaFuncAttributeMaxDynamicSharedMemorySize,
                         GEMM_SMEM);
    cudaFuncSetAttribute(gemm_mma_kernel<1>, cudaFuncAttributeMaxDynamicSharedMemorySize,
                         GEMM_SMEM);

    f16* xh_ptr;      cudaGetSymbolAddress((void**)&xh_ptr, g_xh);
    f16* wh_ptr;      cudaGetSymbolAddress((void**)&wh_ptr, g_wh);
    f16* woh_ptr;     cudaGetSymbolAddress((void**)&woh_ptr, g_woh);
    f16* yh_ptr;      cudaGetSymbolAddress((void**)&yh_ptr, g_yh);

    prep_kernel<<<5120, 256>>>(x, wq, wk, wv, wo);
    gemm_mma_kernel<0><<<dim3(32, 12), 512, GEMM_SMEM>>>(xh_ptr, wh_ptr, nullptr, qnw, knw);
    flash_kernel<<<dim3(16, NH, NB), 128, FLASH_SMEM>>>();
    gemm_mma_kernel<1><<<dim3(32, 8), 512, GEMM_SMEM>>>(yh_ptr, woh_ptr, out, nullptr, nullptr);
}